// round 9
// baseline (speedup 1.0000x reference)
#include <cuda_runtime.h>
#include <cuda_fp16.h>
#include <cstdint>

// ---------------- problem constants ----------------
#define N_ROWS   32768
#define D_IN     256
#define D_HID    1024
#define D_OUT    256
#define N_DOM    8
#define LN_EPS   1e-5f

#define BM 64
#define BN 256
#define BK 32
#define NTHREADS 512
#define MAX_TILES 576
#define RSH 80       // B stage row stride bytes (32 halfs + 16 pad) -> conflict-free
#define XR  528      // x smem row stride bytes (256 halfs + 16 pad) -> conflict-free A frags
#define HR  2064     // h smem row stride bytes (1024 halfs + 16 pad) -> conflict-free A frags

#define SB_ST (BN * RSH)                 // 20480
#define OFF_B    0
#define OFF_X    (2 * SB_ST)             // 40960
#define OFF_H    (OFF_X + BM * XR)       // 74752
#define OFF_G    (OFF_H + BM * HR)       // 206848
#define OFF_BT   (OFF_G + 4096)          // 210944
#define OFF_STAT (OFF_BT + 4096)         // 215040
#define OFF_MU   (OFF_STAT + 2048)       // 217088
#define OFF_RS   (OFF_MU + 256)          // 217344
#define OFF_PERM (OFF_RS + 256)          // 217600
#define SMEM_TOTAL (OFF_PERM + 256)      // 217856

// ---------------- device scratch ----------------
__device__ int g_count[N_DOM], g_offset[N_DOM], g_fill[N_DOM];
__device__ int g_perm[N_ROWS];
__device__ int g_tile_dom[MAX_TILES], g_tile_row[MAX_TILES], g_tile_cnt[MAX_TILES];
__device__ int g_ntiles;
__device__ __align__(16) __half g_w1h[(size_t)N_DOM * D_HID * D_IN];  // [d][n][k]
__device__ __align__(16) __half g_w2h[(size_t)N_DOM * D_OUT * D_HID]; // [d][n][k]

// ---------------- helpers ----------------
__device__ __forceinline__ void mma16(float* c, const uint32_t* a, const uint32_t* b) {
    asm volatile("mma.sync.aligned.m16n8k16.row.col.f32.f16.f16.f32 "
        "{%0,%1,%2,%3}, {%4,%5,%6,%7}, {%8,%9}, {%0,%1,%2,%3};"
        : "+f"(c[0]), "+f"(c[1]), "+f"(c[2]), "+f"(c[3])
        : "r"(a[0]), "r"(a[1]), "r"(a[2]), "r"(a[3]), "r"(b[0]), "r"(b[1]));
}
#define CP16(dst, src) \
    asm volatile("cp.async.cg.shared.global [%0], [%1], 16;" :: "r"(dst), "l"(src) : "memory")
#define CP_COMMIT() asm volatile("cp.async.commit_group;" ::: "memory")
#define CP_WAIT0()  asm volatile("cp.async.wait_group 0;" ::: "memory")

__device__ __forceinline__ uint32_t pack2(float lo, float hi) {
    __half2 h = __floats2half2_rn(lo, hi);
    return *(uint32_t*)&h;
}

// ---------------- sort/plan kernels ----------------
__global__ void init_kernel() {
    int t = threadIdx.x;
    if (t < N_DOM) { g_count[t] = 0; g_fill[t] = 0; }
}
__global__ void hist_kernel(const int* __restrict__ dom) {
    __shared__ int cnt[N_DOM];
    int t = threadIdx.x;
    if (t < N_DOM) cnt[t] = 0;
    __syncthreads();
    int i = blockIdx.x * blockDim.x + t;
    atomicAdd(&cnt[dom[i]], 1);
    __syncthreads();
    if (t < N_DOM && cnt[t] > 0) atomicAdd(&g_count[t], cnt[t]);
}
__global__ void plan_kernel() {
    if (threadIdx.x == 0 && blockIdx.x == 0) {
        int off = 0, nt = 0;
        for (int d = 0; d < N_DOM; d++) {
            g_offset[d] = off;
            int c = g_count[d];
            for (int t = 0; t < c; t += BM) {
                g_tile_dom[nt] = d;
                g_tile_row[nt] = off + t;
                g_tile_cnt[nt] = min(BM, c - t);
                nt++;
            }
            off += c;
        }
        g_ntiles = nt;
    }
}
__global__ void scatter_kernel(const int* __restrict__ dom) {
    __shared__ int cnt[N_DOM], base[N_DOM];
    int t = threadIdx.x;
    if (t < N_DOM) cnt[t] = 0;
    __syncthreads();
    int i = blockIdx.x * blockDim.x + t;
    int d = dom[i];
    int r = atomicAdd(&cnt[d], 1);
    __syncthreads();
    if (t < N_DOM && cnt[t] > 0) base[t] = atomicAdd(&g_fill[t], cnt[t]);
    __syncthreads();
    g_perm[g_offset[d] + base[d] + r] = i;
}

// ---------------- weight transpose+convert: [z][K][N] f32 -> [z][N][K] fp16 ----------------
__global__ void transp_h(const float* __restrict__ src, __half* __restrict__ dst,
                         int K, int N) {
    __shared__ float t[32][33];
    int z = blockIdx.z;
    const float* s = src + (size_t)z * K * N;
    __half* d = dst + (size_t)z * K * N;
    int n0 = blockIdx.x * 32, k0 = blockIdx.y * 32;
    #pragma unroll
    for (int i = threadIdx.y; i < 32; i += 8)
        t[i][threadIdx.x] = s[(size_t)(k0 + i) * N + n0 + threadIdx.x];
    __syncthreads();
    #pragma unroll
    for (int i = threadIdx.y; i < 32; i += 8)
        d[(size_t)(n0 + i) * K + k0 + threadIdx.x] = __float2half_rn(t[threadIdx.x][i]);
}

// ---------------- fragment compute: warp tile 16x64 (mf=1, nf=8) ----------------
#define COMPUTE(Abase_, Ars_, kab_, Bs_, accv_) do {                                   \
    _Pragma("unroll")                                                                   \
    for (int kk = 0; kk < BK; kk += 16) {                                               \
        uint32_t a[4], b[8][2];                                                         \
        const char* A_ = (Abase_) + (wm * 16 + lm) * (Ars_) + ((kab_) + kk + lk * 2) * 2; \
        a[0] = *(const uint32_t*)(A_);                                                  \
        a[1] = *(const uint32_t*)(A_ + 8 * (Ars_));                                     \
        a[2] = *(const uint32_t*)(A_ + 16);                                             \
        a[3] = *(const uint32_t*)(A_ + 8 * (Ars_) + 16);                                \
        _Pragma("unroll")                                                               \
        for (int nf = 0; nf < 8; nf++) {                                                \
            const char* B_ = (Bs_) + (wn * 64 + nf * 8 + lm) * RSH + (kk + lk * 2) * 2; \
            b[nf][0] = *(const uint32_t*)(B_);                                          \
            b[nf][1] = *(const uint32_t*)(B_ + 16);                                     \
        }                                                                               \
        _Pragma("unroll")                                                               \
        for (int nf = 0; nf < 8; nf++)                                                  \
            mma16((accv_)[nf], a, b[nf]);                                               \
    }                                                                                   \
} while (0)

// ============================================================================
// Fused MLP: per 64-row tile — GEMM1 (K=256, N=1024 in 4 col-tiles) -> h in smem
// -> LN+ReLU in smem -> GEMM2 (K=1024, N=256) -> scatter to out
// ============================================================================
__global__ __launch_bounds__(NTHREADS, 1)
void fused_mlp(const float* __restrict__ x,
               const float* __restrict__ b1,
               const float* __restrict__ gamma,
               const float* __restrict__ beta,
               const float* __restrict__ b2,
               float* __restrict__ out) {
    extern __shared__ __align__(16) char smem[];
    uint32_t sbase = (uint32_t)__cvta_generic_to_shared(smem);

    int bt = blockIdx.x;
    if (bt >= g_ntiles) return;
    int dom  = g_tile_dom[bt];
    int row0 = g_tile_row[bt];
    int cnt  = g_tile_cnt[bt];

    int tid  = threadIdx.x;
    int lane = tid & 31, wid = tid >> 5;
    int wm = wid >> 2, wn = wid & 3;
    int lk = lane & 3, lm = lane >> 2;

    int*    sPerm = (int*)(smem + OFF_PERM);
    float*  sG    = (float*)(smem + OFF_G);
    float*  sBt   = (float*)(smem + OFF_BT);
    float*  sMu   = (float*)(smem + OFF_MU);
    float*  sRs   = (float*)(smem + OFF_RS);
    float2* sStat = (float2*)(smem + OFF_STAT);

    if (tid < BM) sPerm[tid] = (tid < cnt) ? g_perm[row0 + tid] : -1;
    for (int i = tid; i < D_HID; i += NTHREADS) {
        sG[i]  = gamma[(size_t)dom * D_HID + i];
        sBt[i] = beta[(size_t)dom * D_HID + i];
    }
    __syncthreads();

    const __half* W1p = g_w1h + (size_t)dom * D_HID * D_IN;
    const __half* W2p = g_w2h + (size_t)dom * D_OUT * D_HID;
    int bn = tid >> 1, bj = tid & 1;

    #define ISSUE1(cidx) do {                                                          \
        int ct_ = (cidx) >> 3, kc_ = (cidx) & 7;                                       \
        uint32_t sb = sbase + OFF_B + ((cidx) & 1) * SB_ST;                            \
        const __half* bs = W1p + (size_t)(ct_ * 256 + bn) * D_IN + kc_ * 32 + bj * 16; \
        CP16(sb + bn * RSH + bj * 32,      bs);                                        \
        CP16(sb + bn * RSH + bj * 32 + 16, bs + 8);                                    \
        CP_COMMIT();                                                                   \
    } while (0)

    #define ISSUE2(cidx) do {                                                          \
        uint32_t sb = sbase + OFF_B + ((cidx) & 1) * SB_ST;                            \
        const __half* bs = W2p + (size_t)bn * D_HID + (cidx) * 32 + bj * 16;           \
        CP16(sb + bn * RSH + bj * 32,      bs);                                        \
        CP16(sb + bn * RSH + bj * 32 + 16, bs + 8);                                    \
        CP_COMMIT();                                                                   \
    } while (0)

    // prefetch first W1 chunk, then load+convert x tile (overlaps cp.async latency)
    ISSUE1(0);
    {
        int row = tid >> 3, seg = tid & 7;
        int src = sPerm[row];
        char* xd = smem + OFF_X + row * XR + seg * 64;
        if (src >= 0) {
            const float4* sp = (const float4*)(x + (size_t)src * D_IN + seg * 32);
            #pragma unroll
            for (int j = 0; j < 4; j++) {
                float4 v0 = sp[2 * j], v1 = sp[2 * j + 1];
                uint4 o;
                o.x = pack2(v0.x, v0.y); o.y = pack2(v0.z, v0.w);
                o.z = pack2(v1.x, v1.y); o.w = pack2(v1.z, v1.w);
                *(uint4*)(xd + j * 16) = o;
            }
        } else {
            uint4 z = make_uint4(0, 0, 0, 0);
            #pragma unroll
            for (int j = 0; j < 4; j++) *(uint4*)(xd + j * 16) = z;
        }
    }
    __syncthreads();

    // ---------------- phase 1: h = x @ W1^T + b1 (4 col-tiles) ----------------
    float myS[2] = {0.f, 0.f}, mySS[2] = {0.f, 0.f};
    for (int ct = 0; ct < 4; ct++) {
        float acc[8][4];
        #pragma unroll
        for (int j = 0; j < 8; j++)
            #pragma unroll
            for (int q = 0; q < 4; q++) acc[j][q] = 0.f;

        for (int kc = 0; kc < 8; kc++) {
            int c = ct * 8 + kc;
            CP_WAIT0();
            __syncthreads();
            if (c + 1 < 32) ISSUE1(c + 1);
            COMPUTE(smem + OFF_X, XR, kc * 32, smem + OFF_B + (c & 1) * SB_ST, acc);
        }

        // epilogue ct: bias, write fp16 h to smem, accumulate stats
        const float* b1d = b1 + (size_t)dom * D_HID + ct * 256 + wn * 64;
        #pragma unroll
        for (int rsel = 0; rsel < 2; rsel++) {
            int r = wm * 16 + lm + rsel * 8;
            char* hrow = smem + OFF_H + r * HR + (ct * 256 + wn * 64) * 2;
            float s = 0.f, ss = 0.f;
            #pragma unroll
            for (int nf = 0; nf < 8; nf++) {
                int cc = nf * 8 + 2 * lk;
                float v0 = acc[nf][rsel * 2 + 0] + __ldg(b1d + cc);
                float v1 = acc[nf][rsel * 2 + 1] + __ldg(b1d + cc + 1);
                s += v0 + v1;
                ss += v0 * v0 + v1 * v1;
                *(uint32_t*)(hrow + cc * 2) = pack2(v0, v1);
            }
            myS[rsel] += s; mySS[rsel] += ss;
        }
    }
    #undef ISSUE1

    // ---------------- stats reduce + LN in smem ----------------
    #pragma unroll
    for (int rsel = 0; rsel < 2; rsel++) {
        float s = myS[rsel], ss = mySS[rsel];
        s  += __shfl_xor_sync(0xffffffffu, s, 1);
        s  += __shfl_xor_sync(0xffffffffu, s, 2);
        ss += __shfl_xor_sync(0xffffffffu, ss, 1);
        ss += __shfl_xor_sync(0xffffffffu, ss, 2);
        if (lk == 0) sStat[(wm * 16 + lm + rsel * 8) * 4 + wn] = make_float2(s, ss);
    }
    __syncthreads();

    ISSUE2(0);   // prefetch first W2 chunk; LN pass hides the latency

    if (tid < BM) {
        float s = 0.f, ss = 0.f;
        #pragma unroll
        for (int q = 0; q < 4; q++) {
            float2 p = sStat[tid * 4 + q];
            s += p.x; ss += p.y;
        }
        float mu = s * (1.f / D_HID);
        float var = ss * (1.f / D_HID) - mu * mu;
        sMu[tid] = mu;
        sRs[tid] = rsqrtf(var + LN_EPS);
    }
    __syncthreads();

    {
        int row = tid >> 3, seg = tid & 7;
        float mu = sMu[row], rs = sRs[row];
        char* hp = smem + OFF_H + row * HR + seg * 256;
        int kb0 = seg * 128;
        #pragma unroll
        for (int u = 0; u < 16; u++) {
            int uu = (u + seg * 2) & 15;     // de-phase segs to spread banks
            char* p = hp + uu * 16;
            uint4 hv = *(uint4*)p;
            int kb = kb0 + uu * 8;
            uint32_t hw[4] = {hv.x, hv.y, hv.z, hv.w};
            uint32_t ow[4];
            #pragma unroll
            for (int j = 0; j < 4; j++) {
                float2 f = __half22float2(*(__half2*)&hw[j]);
                float a0 = fmaxf(fmaf((f.x - mu) * rs, sG[kb + 2 * j],     sBt[kb + 2 * j]),     0.f);
                float a1 = fmaxf(fmaf((f.y - mu) * rs, sG[kb + 2 * j + 1], sBt[kb + 2 * j + 1]), 0.f);
                ow[j] = pack2(a0, a1);
            }
            *(uint4*)p = make_uint4(ow[0], ow[1], ow[2], ow[3]);
        }
    }
    __syncthreads();

    // ---------------- phase 2: out = h_ln @ W2^T + b2 ----------------
    float acc2[8][4];
    #pragma unroll
    for (int j = 0; j < 8; j++)
        #pragma unroll
        for (int q = 0; q < 4; q++) acc2[j][q] = 0.f;

    for (int c = 0; c < 32; c++) {
        CP_WAIT0();
        __syncthreads();
        if (c + 1 < 32) ISSUE2(c + 1);
        COMPUTE(smem + OFF_H, HR, c * 32, smem + OFF_B + (c & 1) * SB_ST, acc2);
    }
    #undef ISSUE2

    // epilogue: bias, scatter to out
    const float* b2d = b2 + (size_t)dom * D_OUT + wn * 64;
    #pragma unroll
    for (int rsel = 0; rsel < 2; rsel++) {
        int r = wm * 16 + lm + rsel * 8;
        int src = sPerm[r];
        if (src < 0) continue;
        float* orow = out + (size_t)src * D_OUT + wn * 64;
        #pragma unroll
        for (int nf = 0; nf < 8; nf++) {
            int cc = nf * 8 + 2 * lk;
            float v0 = acc2[nf][rsel * 2 + 0] + __ldg(b2d + cc);
            float v1 = acc2[nf][rsel * 2 + 1] + __ldg(b2d + cc + 1);
            *(float2*)(orow + cc) = make_float2(v0, v1);
        }
    }
}

// ---------------- launch ----------------
extern "C" void kernel_launch(void* const* d_in, const int* in_sizes, int n_in,
                              void* d_out, int out_size) {
    const float* x     = (const float*)d_in[0];
    const int*   dom   = (const int*)  d_in[1];
    const float* W1    = (const float*)d_in[2];
    const float* b1    = (const float*)d_in[3];
    const float* gamma = (const float*)d_in[4];
    const float* beta  = (const float*)d_in[5];
    const float* W2    = (const float*)d_in[6];
    const float* b2    = (const float*)d_in[7];
    float* out = (float*)d_out;

    cudaFuncSetAttribute(fused_mlp, cudaFuncAttributeMaxDynamicSharedMemorySize, SMEM_TOTAL);

    init_kernel<<<1, 32>>>();
    hist_kernel<<<N_ROWS / 256, 256>>>(dom);
    plan_kernel<<<1, 32>>>();
    scatter_kernel<<<N_ROWS / 256, 256>>>(dom);

    {   // weights: transpose + fp16
        __half* w1h; cudaGetSymbolAddress((void**)&w1h, g_w1h);
        __half* w2h; cudaGetSymbolAddress((void**)&w2h, g_w2h);
        dim3 blk(32, 8);
        dim3 t1(D_HID / 32, D_IN / 32, N_DOM);
        transp_h<<<t1, blk>>>(W1, w1h, D_IN, D_HID);
        dim3 t2(D_OUT / 32, D_HID / 32, N_DOM);
        transp_h<<<t2, blk>>>(W2, w2h, D_HID, D_OUT);
    }

    fused_mlp<<<MAX_TILES, NTHREADS, SMEM_TOTAL>>>(x, b1, gamma, beta, b2, out);
}

// round 10
// speedup vs baseline: 1.4720x; 1.4720x over previous
#include <cuda_runtime.h>
#include <cuda_fp16.h>
#include <cstdint>

// ---------------- problem constants ----------------
#define N_ROWS   32768
#define D_IN     256
#define D_HID    1024
#define D_OUT    256
#define N_DOM    8
#define LN_EPS   1e-5f

#define BM 128
#define BN 256
#define BK 32
#define NTHREADS 512
#define MAX_TILES 384
#define RSH 80             // smem row stride in BYTES (32 halfs data + 8 pad)

#define SA_ST (BM * RSH)   // 10240 B per A slot
#define SB_ST (BN * RSH)   // 20480 B per B stage

// GEMM1: 2-slot A (register-staged gather+cvt), 3-stage B
#define OFF1_A 0
#define OFF1_B (2 * SA_ST)                        // 20480
#define END1   (OFF1_B + 3 * SB_ST)               // 81920
#define G1_PERM END1
#define G1_STAT (END1 + 512)
#define SMEM1_TOTAL (END1 + 512 + 4096)           // 86528

// GEMM2: 2-slot A (LN loader), 3-stage B
#define OFF2_A 0
#define OFF2_B (2 * SA_ST)                        // 20480
#define END2   (OFF2_B + 3 * SB_ST)               // 81920
#define G2_G    END2
#define G2_B    (END2 + 4096)
#define G2_MU   (END2 + 8192)
#define G2_RS   (END2 + 8704)
#define G2_PERM (END2 + 9216)
#define SMEM2_TOTAL (END2 + 9728)                 // 91648

// ---------------- device scratch ----------------
__device__ int g_count[N_DOM], g_offset[N_DOM], g_fill[N_DOM];
__device__ int g_perm[N_ROWS];
__device__ int g_tile_dom[MAX_TILES], g_tile_row[MAX_TILES], g_tile_cnt[MAX_TILES];
__device__ int g_ntiles;
__device__ __align__(16) __half g_hh[(size_t)N_ROWS * D_HID];     // fp16 h+bias
__device__ __align__(16) float2 g_part[(size_t)N_ROWS * 4];
__device__ __align__(16) __half g_w1h[(size_t)N_DOM * D_HID * D_IN];  // [d][n][k] fp16
__device__ __align__(16) __half g_w2h[(size_t)N_DOM * D_OUT * D_HID]; // [d][n][k] fp16

// ---------------- helpers ----------------
__device__ __forceinline__ void mma16(float* c, const uint32_t* a, const uint32_t* b) {
    asm volatile("mma.sync.aligned.m16n8k16.row.col.f32.f16.f16.f32 "
        "{%0,%1,%2,%3}, {%4,%5,%6,%7}, {%8,%9}, {%0,%1,%2,%3};"
        : "+f"(c[0]), "+f"(c[1]), "+f"(c[2]), "+f"(c[3])
        : "r"(a[0]), "r"(a[1]), "r"(a[2]), "r"(a[3]), "r"(b[0]), "r"(b[1]));
}
#define LDSM4(r0, r1, r2, r3, addr) \
    asm volatile("ldmatrix.sync.aligned.m8n8.x4.shared.b16 {%0,%1,%2,%3}, [%4];" \
        : "=r"(r0), "=r"(r1), "=r"(r2), "=r"(r3) : "r"(addr))
#define CP16(dst, src) \
    asm volatile("cp.async.cg.shared.global [%0], [%1], 16;" :: "r"(dst), "l"(src) : "memory")
#define CP_COMMIT() asm volatile("cp.async.commit_group;" ::: "memory")
#define CP_WAIT1()  asm volatile("cp.async.wait_group 1;" ::: "memory")

__device__ __forceinline__ uint32_t pack2(float lo, float hi) {
    __half2 h = __floats2half2_rn(lo, hi);
    return *(uint32_t*)&h;
}

// ---------------- sort/plan kernels ----------------
__global__ void init_kernel() {
    int t = threadIdx.x;
    if (t < N_DOM) { g_count[t] = 0; g_fill[t] = 0; }
}
__global__ void hist_kernel(const int* __restrict__ dom) {
    __shared__ int cnt[N_DOM];
    int t = threadIdx.x;
    if (t < N_DOM) cnt[t] = 0;
    __syncthreads();
    int i = blockIdx.x * blockDim.x + t;
    atomicAdd(&cnt[dom[i]], 1);
    __syncthreads();
    if (t < N_DOM && cnt[t] > 0) atomicAdd(&g_count[t], cnt[t]);
}
__global__ void plan_kernel() {
    if (threadIdx.x == 0 && blockIdx.x == 0) {
        int off = 0, nt = 0;
        for (int d = 0; d < N_DOM; d++) {
            g_offset[d] = off;
            int c = g_count[d];
            for (int t = 0; t < c; t += BM) {
                g_tile_dom[nt] = d;
                g_tile_row[nt] = off + t;
                g_tile_cnt[nt] = min(BM, c - t);
                nt++;
            }
            off += c;
        }
        g_ntiles = nt;
    }
}
__global__ void scatter_kernel(const int* __restrict__ dom) {
    __shared__ int cnt[N_DOM], base[N_DOM];
    int t = threadIdx.x;
    if (t < N_DOM) cnt[t] = 0;
    __syncthreads();
    int i = blockIdx.x * blockDim.x + t;
    int d = dom[i];
    int r = atomicAdd(&cnt[d], 1);
    __syncthreads();
    if (t < N_DOM && cnt[t] > 0) base[t] = atomicAdd(&g_fill[t], cnt[t]);
    __syncthreads();
    g_perm[g_offset[d] + base[d] + r] = i;
}

// ---------------- weight transpose+convert: [z][K][N] f32 -> [z][N][K] fp16 ----------------
__global__ void transp_h(const float* __restrict__ src, __half* __restrict__ dst,
                         int K, int N) {
    __shared__ float t[32][33];
    int z = blockIdx.z;
    const float* s = src + (size_t)z * K * N;
    __half* d = dst + (size_t)z * K * N;
    int n0 = blockIdx.x * 32, k0 = blockIdx.y * 32;
    #pragma unroll
    for (int i = threadIdx.y; i < 32; i += 8)
        t[i][threadIdx.x] = s[(size_t)(k0 + i) * N + n0 + threadIdx.x];
    __syncthreads();
    #pragma unroll
    for (int i = threadIdx.y; i < 32; i += 8)
        d[(size_t)(n0 + i) * K + k0 + threadIdx.x] = __float2half_rn(t[threadIdx.x][i]);
}

// ---------------- fragment compute: 16 warps, warp tile 32x64 (mf=2, nf=8) ----------------
// ldmatrix-based fragment loads. A addr lane pattern: row = lane&15, kblk = lane>>4.
// B addr lane pattern: n = (lane>>4)*8 + (lane&7), kblk = (lane>>3)&1.
#define COMPUTE_FRAGS(AsOff_, BsOff_) do {                                             \
    uint32_t aA = sbase + (AsOff_) + (wm * 32 + (lane & 15)) * RSH + ((lane >> 4) * 8) * 2; \
    uint32_t aB = sbase + (BsOff_) + (wn * 64 + ((lane >> 4) * 8) + (lane & 7)) * RSH       \
                  + (((lane >> 3) & 1) * 8) * 2;                                        \
    _Pragma("unroll")                                                                   \
    for (int kk = 0; kk < BK; kk += 16) {                                               \
        uint32_t a[2][4], b[8][2];                                                      \
        LDSM4(a[0][0], a[0][1], a[0][2], a[0][3], aA + kk * 2);                         \
        LDSM4(a[1][0], a[1][1], a[1][2], a[1][3], aA + 16 * RSH + kk * 2);              \
        LDSM4(b[0][0], b[0][1], b[1][0], b[1][1], aB + kk * 2);                         \
        LDSM4(b[2][0], b[2][1], b[3][0], b[3][1], aB + 16 * RSH + kk * 2);              \
        LDSM4(b[4][0], b[4][1], b[5][0], b[5][1], aB + 32 * RSH + kk * 2);              \
        LDSM4(b[6][0], b[6][1], b[7][0], b[7][1], aB + 48 * RSH + kk * 2);              \
        _Pragma("unroll")                                                               \
        for (int mf = 0; mf < 2; mf++)                                                  \
            _Pragma("unroll")                                                           \
            for (int nf = 0; nf < 8; nf++)                                              \
                mma16(acc[mf][nf], a[mf], b[nf]);                                       \
    }                                                                                   \
} while (0)

// ============================================================================
// GEMM1: h = fp16(x[perm]) @ W1h[d]^T + b1 -> g_hh; per-row (sum,sumsq)
// 512 threads; A: fused gather+cvt (2-slot); B: 3-stage cp.async
// ============================================================================
__global__ __launch_bounds__(NTHREADS, 1)
void gemm1_h(const float* __restrict__ x,
             const float* __restrict__ b1) {
    extern __shared__ __align__(16) char smem[];
    uint32_t sbase = (uint32_t)__cvta_generic_to_shared(smem);
    int*    sPerm = (int*)(smem + G1_PERM);
    float2* sStat = (float2*)(smem + G1_STAT);

    int bt = blockIdx.x;
    if (bt >= g_ntiles) return;
    int dom  = g_tile_dom[bt];
    int row0 = g_tile_row[bt];
    int cnt  = g_tile_cnt[bt];
    int by   = blockIdx.y;
    int colBase = by * BN;

    int tid  = threadIdx.x;
    int lane = tid & 31, wid = tid >> 5;
    int wm = wid >> 2, wn = wid & 3;
    int lk = lane & 3, lm = lane >> 2;

    if (tid < BM) sPerm[tid] = (tid < cnt) ? g_perm[row0 + tid] : -1;
    __syncthreads();

    const __half* W1h = g_w1h + ((size_t)dom * D_HID + colBase) * D_IN;

    // A loader: row = tid>>2 (0..127), seg = tid&3 (8 floats -> 8 halfs)
    int arow = tid >> 2, aseg = tid & 3;
    int asrc = sPerm[arow];
    // B loader: n = tid>>1 (0..255), half of 64B row
    int bn = tid >> 1, bj = tid & 1;

    #define ISSUE1B(cidx) do {                                                         \
        int k0_ = (cidx) * BK;                                                         \
        uint32_t sb = sbase + OFF1_B + ((cidx) % 3) * SB_ST;                           \
        const __half* bsrc = W1h + (size_t)bn * D_IN + k0_ + bj * 16;                  \
        CP16(sb + bn * RSH + bj * 32,      bsrc);                                      \
        CP16(sb + bn * RSH + bj * 32 + 16, bsrc + 8);                                  \
        CP_COMMIT();                                                                   \
    } while (0)

    float4 xv0, xv1;
    #define LDG_A1(k0_) do {                                                           \
        if (asrc >= 0) {                                                               \
            const float* sp = x + (size_t)asrc * D_IN + (k0_) + aseg * 8;              \
            xv0 = *(const float4*)(sp);                                                \
            xv1 = *(const float4*)(sp + 4);                                            \
        } else {                                                                       \
            xv0 = make_float4(0.f, 0.f, 0.f, 0.f);                                     \
            xv1 = xv0;                                                                 \
        }                                                                              \
    } while (0)

    #define PREP_STS_A1(slot) do {                                                     \
        uint4 o;                                                                       \
        o.x = pack2(xv0.x, xv0.y); o.y = pack2(xv0.z, xv0.w);                          \
        o.z = pack2(xv1.x, xv1.y); o.w = pack2(xv1.z, xv1.w);                          \
        *(uint4*)(smem + OFF1_A + (slot) * SA_ST + arow * RSH + aseg * 16) = o;        \
    } while (0)

    float acc[2][8][4];
    #pragma unroll
    for (int i = 0; i < 2; i++)
        #pragma unroll
        for (int j = 0; j < 8; j++)
            #pragma unroll
            for (int q = 0; q < 4; q++) acc[i][j][q] = 0.f;

    ISSUE1B(0); ISSUE1B(1);
    LDG_A1(0);
    PREP_STS_A1(0);

    const int NC = D_IN / BK;  // 8
    for (int c = 0; c < NC; c++) {
        CP_WAIT1();
        __syncthreads();
        if (c + 2 < NC) ISSUE1B(c + 2); else CP_COMMIT();
        if (c + 1 < NC) LDG_A1((c + 1) * BK);
        COMPUTE_FRAGS(OFF1_A + (c & 1) * SA_ST, OFF1_B + (c % 3) * SB_ST);
        if (c + 1 < NC) PREP_STS_A1((c + 1) & 1);
    }
    #undef ISSUE1B
    #undef LDG_A1
    #undef PREP_STS_A1

    // ---- epilogue: bias add, store fp16 h, per-row stats ----
    __syncthreads();
    const float* b1d = b1 + (size_t)dom * D_HID + colBase + wn * 64;
    #pragma unroll
    for (int mf = 0; mf < 2; mf++) {
        #pragma unroll
        for (int rsel = 0; rsel < 2; rsel++) {
            int r = wm * 32 + mf * 16 + lm + rsel * 8;
            float s = 0.f, ss = 0.f;
            __half* hrow = g_hh + (size_t)(row0 + r) * D_HID + colBase + wn * 64;
            bool wr = (r < cnt);
            #pragma unroll
            for (int nf = 0; nf < 8; nf++) {
                int cc = nf * 8 + 2 * lk;
                float v0 = acc[mf][nf][rsel * 2 + 0] + __ldg(b1d + cc);
                float v1 = acc[mf][nf][rsel * 2 + 1] + __ldg(b1d + cc + 1);
                s += v0 + v1;
                ss += v0 * v0 + v1 * v1;
                if (wr) *(uint32_t*)(hrow + cc) = pack2(v0, v1);
            }
            s  += __shfl_xor_sync(0xffffffffu, s, 1);
            s  += __shfl_xor_sync(0xffffffffu, s, 2);
            ss += __shfl_xor_sync(0xffffffffu, ss, 1);
            ss += __shfl_xor_sync(0xffffffffu, ss, 2);
            if (lk == 0) sStat[r * 4 + wn] = make_float2(s, ss);
        }
    }
    __syncthreads();
    if (tid < BM && tid < cnt) {
        float s = 0.f, ss = 0.f;
        #pragma unroll
        for (int q = 0; q < 4; q++) {
            float2 p = sStat[tid * 4 + q];
            s += p.x; ss += p.y;
        }
        g_part[(size_t)(row0 + tid) * 4 + by] = make_float2(s, ss);
    }
}

// ============================================================================
// GEMM2: out[perm] = relu(LN(h)*gamma+beta) @ W2h[d]^T + b2
// 512 threads; A: fused LN loader (2-slot); B: 3-stage cp.async
// ============================================================================
__global__ __launch_bounds__(NTHREADS, 1)
void gemm2_h(const float* __restrict__ gamma,
             const float* __restrict__ beta,
             const float* __restrict__ b2,
             float* __restrict__ out) {
    extern __shared__ __align__(16) char smem[];
    uint32_t sbase = (uint32_t)__cvta_generic_to_shared(smem);
    float* sG  = (float*)(smem + G2_G);
    float* sBt = (float*)(smem + G2_B);
    float* sMu = (float*)(smem + G2_MU);
    float* sRs = (float*)(smem + G2_RS);
    int*   sPerm = (int*)(smem + G2_PERM);

    int bt = blockIdx.x;
    if (bt >= g_ntiles) return;
    int dom  = g_tile_dom[bt];
    int row0 = g_tile_row[bt];
    int cnt  = g_tile_cnt[bt];

    int tid  = threadIdx.x;
    int lane = tid & 31, wid = tid >> 5;
    int wm = wid >> 2, wn = wid & 3;
    int lk = lane & 3, lm = lane >> 2;

    for (int i = tid; i < D_HID; i += NTHREADS) {
        sG[i]  = gamma[(size_t)dom * D_HID + i];
        sBt[i] = beta[(size_t)dom * D_HID + i];
    }
    if (tid < BM) {
        sPerm[tid] = (tid < cnt) ? g_perm[row0 + tid] : -1;
        float mu = 0.f, rs = 0.f;
        if (tid < cnt) {
            float s = 0.f, ss = 0.f;
            #pragma unroll
            for (int q = 0; q < 4; q++) {
                float2 p = g_part[(size_t)(row0 + tid) * 4 + q];
                s += p.x; ss += p.y;
            }
            mu = s * (1.f / D_HID);
            float var = ss * (1.f / D_HID) - mu * mu;
            rs = rsqrtf(var + LN_EPS);
        }
        sMu[tid] = mu; sRs[tid] = rs;
    }
    __syncthreads();

    const __half* W2h = g_w2h + (size_t)dom * D_OUT * D_HID;

    // A loader: row = tid>>2, 8 halfs at (tid&3)*8
    int arow = tid >> 2, aseg = tid & 3;
    int icl = min(arow, cnt - 1);
    int iar = row0 + icl;
    float amu = sMu[icl], ars = sRs[icl];
    // B loader: n = tid>>1, half of 64B row
    int bn = tid >> 1, bj = tid & 1;

    #define ISSUE2B(cidx) do {                                                         \
        int k0_ = (cidx) * BK;                                                         \
        uint32_t sb = sbase + OFF2_B + ((cidx) % 3) * SB_ST;                           \
        const __half* bsrc = W2h + (size_t)bn * D_HID + k0_ + bj * 16;                 \
        CP16(sb + bn * RSH + bj * 32,      bsrc);                                      \
        CP16(sb + bn * RSH + bj * 32 + 16, bsrc + 8);                                  \
        CP_COMMIT();                                                                   \
    } while (0)

    uint4 hv;
    #define LDG_A2(k0_) do {                                                           \
        hv = *(const uint4*)(g_hh + (size_t)iar * D_HID + (k0_) + aseg * 8);           \
    } while (0)

    #define LN1(f, kb) fmaxf(fmaf(((f) - amu) * ars, sG[kb], sBt[kb]), 0.f)

    #define PREP_STS_A2(slot, k0_) do {                                                \
        int kb = (k0_) + aseg * 8;                                                     \
        uint32_t hw[4] = {hv.x, hv.y, hv.z, hv.w};                                     \
        uint32_t ow[4];                                                                \
        _Pragma("unroll")                                                              \
        for (int j_ = 0; j_ < 4; j_++) {                                               \
            float2 f = __half22float2(*(__half2*)&hw[j_]);                             \
            ow[j_] = pack2(LN1(f.x, kb + 2 * j_), LN1(f.y, kb + 2 * j_ + 1));          \
        }                                                                              \
        *(uint4*)(smem + OFF2_A + (slot) * SA_ST + arow * RSH + aseg * 16) =           \
            make_uint4(ow[0], ow[1], ow[2], ow[3]);                                    \
    } while (0)

    float acc[2][8][4];
    #pragma unroll
    for (int i = 0; i < 2; i++)
        #pragma unroll
        for (int j = 0; j < 8; j++)
            #pragma unroll
            for (int q = 0; q < 4; q++) acc[i][j][q] = 0.f;

    ISSUE2B(0); ISSUE2B(1);
    LDG_A2(0);
    PREP_STS_A2(0, 0);

    const int NC = D_HID / BK;  // 32
    for (int c = 0; c < NC; c++) {
        CP_WAIT1();
        __syncthreads();
        if (c + 2 < NC) ISSUE2B(c + 2); else CP_COMMIT();
        if (c + 1 < NC) LDG_A2((c + 1) * BK);
        COMPUTE_FRAGS(OFF2_A + (c & 1) * SA_ST, OFF2_B + (c % 3) * SB_ST);
        if (c + 1 < NC) PREP_STS_A2((c + 1) & 1, (c + 1) * BK);
    }
    #undef ISSUE2B
    #undef LDG_A2
    #undef LN1
    #undef PREP_STS_A2

    // ---- epilogue: bias add, scatter to out ----
    const float* b2d = b2 + (size_t)dom * D_OUT + wn * 64;
    #pragma unroll
    for (int mf = 0; mf < 2; mf++) {
        #pragma unroll
        for (int rsel = 0; rsel < 2; rsel++) {
            int r = wm * 32 + mf * 16 + lm + rsel * 8;
            int src = sPerm[r];
            if (src < 0) continue;
            float* orow = out + (size_t)src * D_OUT + wn * 64;
            #pragma unroll
            for (int nf = 0; nf < 8; nf++) {
                int cc = nf * 8 + 2 * lk;
                float v0 = acc[mf][nf][rsel * 2 + 0] + __ldg(b2d + cc);
                float v1 = acc[mf][nf][rsel * 2 + 1] + __ldg(b2d + cc + 1);
                *(float2*)(orow + cc) = make_float2(v0, v1);
            }
        }
    }
}

// ---------------- launch ----------------
extern "C" void kernel_launch(void* const* d_in, const int* in_sizes, int n_in,
                              void* d_out, int out_size) {
    const float* x     = (const float*)d_in[0];
    const int*   dom   = (const int*)  d_in[1];
    const float* W1    = (const float*)d_in[2];
    const float* b1    = (const float*)d_in[3];
    const float* gamma = (const float*)d_in[4];
    const float* beta  = (const float*)d_in[5];
    const float* W2    = (const float*)d_in[6];
    const float* b2    = (const float*)d_in[7];
    float* out = (float*)d_out;

    cudaFuncSetAttribute(gemm1_h, cudaFuncAttributeMaxDynamicSharedMemorySize, SMEM1_TOTAL);
    cudaFuncSetAttribute(gemm2_h, cudaFuncAttributeMaxDynamicSharedMemorySize, SMEM2_TOTAL);

    init_kernel<<<1, 32>>>();
    hist_kernel<<<N_ROWS / 256, 256>>>(dom);
    plan_kernel<<<1, 32>>>();
    scatter_kernel<<<N_ROWS / 256, 256>>>(dom);

    {   // weights: transpose + fp16
        __half* w1h; cudaGetSymbolAddress((void**)&w1h, g_w1h);
        __half* w2h; cudaGetSymbolAddress((void**)&w2h, g_w2h);
        dim3 blk(32, 8);
        dim3 t1(D_HID / 32, D_IN / 32, N_DOM);
        transp_h<<<t1, blk>>>(W1, w1h, D_IN, D_HID);
        dim3 t2(D_OUT / 32, D_HID / 32, N_DOM);
        transp_h<<<t2, blk>>>(W2, w2h, D_HID, D_OUT);
    }

    dim3 grid1(MAX_TILES, D_HID / BN);   // (384, 4)
    gemm1_h<<<grid1, NTHREADS, SMEM1_TOTAL>>>(x, b1);

    gemm2_h<<<MAX_TILES, NTHREADS, SMEM2_TOTAL>>>(gamma, beta, b2, out);
}

// round 11
// speedup vs baseline: 1.4833x; 1.0077x over previous
#include <cuda_runtime.h>
#include <cuda_fp16.h>
#include <cstdint>

// ---------------- problem constants ----------------
#define N_ROWS   32768
#define D_IN     256
#define D_HID    1024
#define D_OUT    256
#define N_DOM    8
#define LN_EPS   1e-5f

#define BM 128
#define BN 256
#define BK 32
#define NTHREADS 512
#define MAX_TILES 384
#define RSH 80             // smem row stride in BYTES (32 halfs data + 8 pad)

#define SA_ST (BM * RSH)   // 10240 B per A slot
#define SB_ST (BN * RSH)   // 20480 B per B stage

// GEMM1: 2-slot A (register-staged gather+cvt), 3-stage B
#define OFF1_A 0
#define OFF1_B (2 * SA_ST)                        // 20480
#define END1   (OFF1_B + 3 * SB_ST)               // 81920
#define G1_PERM END1
#define G1_STAT (END1 + 512)
#define SMEM1_TOTAL (END1 + 512 + 4096)           // 86528

// GEMM2: 2-slot A (LN loader), 3-stage B
#define OFF2_A 0
#define OFF2_B (2 * SA_ST)                        // 20480
#define END2   (OFF2_B + 3 * SB_ST)               // 81920
#define G2_G    END2
#define G2_B    (END2 + 4096)
#define G2_MU   (END2 + 8192)
#define G2_RS   (END2 + 8704)
#define G2_PERM (END2 + 9216)
#define SMEM2_TOTAL (END2 + 9728)                 // 91648

// ---------------- device scratch ----------------
__device__ int g_count[N_DOM], g_offset[N_DOM], g_fill[N_DOM];
__device__ int g_perm[N_ROWS];
__device__ int g_tile_dom[MAX_TILES], g_tile_row[MAX_TILES], g_tile_cnt[MAX_TILES];
__device__ int g_ntiles;
__device__ __align__(16) __half g_hh[(size_t)N_ROWS * D_HID];     // fp16 h+bias
__device__ __align__(16) float2 g_part[(size_t)N_ROWS * 4];
__device__ __align__(16) __half g_w1h[(size_t)N_DOM * D_HID * D_IN];  // [d][n][k] fp16
__device__ __align__(16) __half g_w2h[(size_t)N_DOM * D_OUT * D_HID]; // [d][n][k] fp16

// ---------------- helpers ----------------
__device__ __forceinline__ void mma16(float* c, const uint32_t* a, const uint32_t* b) {
    asm volatile("mma.sync.aligned.m16n8k16.row.col.f32.f16.f16.f32 "
        "{%0,%1,%2,%3}, {%4,%5,%6,%7}, {%8,%9}, {%0,%1,%2,%3};"
        : "+f"(c[0]), "+f"(c[1]), "+f"(c[2]), "+f"(c[3])
        : "r"(a[0]), "r"(a[1]), "r"(a[2]), "r"(a[3]), "r"(b[0]), "r"(b[1]));
}
#define LDSM4(r0, r1, r2, r3, addr) \
    asm volatile("ldmatrix.sync.aligned.m8n8.x4.shared.b16 {%0,%1,%2,%3}, [%4];" \
        : "=r"(r0), "=r"(r1), "=r"(r2), "=r"(r3) : "r"(addr))
#define CP16(dst, src) \
    asm volatile("cp.async.cg.shared.global [%0], [%1], 16;" :: "r"(dst), "l"(src) : "memory")
#define CP_COMMIT() asm volatile("cp.async.commit_group;" ::: "memory")
#define CP_WAIT1()  asm volatile("cp.async.wait_group 1;" ::: "memory")

__device__ __forceinline__ uint32_t pack2(float lo, float hi) {
    __half2 h = __floats2half2_rn(lo, hi);
    return *(uint32_t*)&h;
}

// ---------------- sort/plan kernels ----------------
__global__ void init_kernel() {
    int t = threadIdx.x;
    if (t < N_DOM) { g_count[t] = 0; g_fill[t] = 0; }
}
__global__ void hist_kernel(const int* __restrict__ dom) {
    __shared__ int cnt[N_DOM];
    int t = threadIdx.x;
    if (t < N_DOM) cnt[t] = 0;
    __syncthreads();
    int i = blockIdx.x * blockDim.x + t;
    atomicAdd(&cnt[dom[i]], 1);
    __syncthreads();
    if (t < N_DOM && cnt[t] > 0) atomicAdd(&g_count[t], cnt[t]);
}
__global__ void plan_kernel() {
    if (threadIdx.x == 0 && blockIdx.x == 0) {
        int off = 0, nt = 0;
        for (int d = 0; d < N_DOM; d++) {
            g_offset[d] = off;
            int c = g_count[d];
            for (int t = 0; t < c; t += BM) {
                g_tile_dom[nt] = d;
                g_tile_row[nt] = off + t;
                g_tile_cnt[nt] = min(BM, c - t);
                nt++;
            }
            off += c;
        }
        g_ntiles = nt;
    }
}
__global__ void scatter_kernel(const int* __restrict__ dom) {
    __shared__ int cnt[N_DOM], base[N_DOM];
    int t = threadIdx.x;
    if (t < N_DOM) cnt[t] = 0;
    __syncthreads();
    int i = blockIdx.x * blockDim.x + t;
    int d = dom[i];
    int r = atomicAdd(&cnt[d], 1);
    __syncthreads();
    if (t < N_DOM && cnt[t] > 0) base[t] = atomicAdd(&g_fill[t], cnt[t]);
    __syncthreads();
    g_perm[g_offset[d] + base[d] + r] = i;
}

// ---------------- weight transpose+convert: [z][K][N] f32 -> [z][N][K] fp16 ----------------
__global__ void transp_h(const float* __restrict__ src, __half* __restrict__ dst,
                         int K, int N) {
    __shared__ float t[32][33];
    int z = blockIdx.z;
    const float* s = src + (size_t)z * K * N;
    __half* d = dst + (size_t)z * K * N;
    int n0 = blockIdx.x * 32, k0 = blockIdx.y * 32;
    #pragma unroll
    for (int i = threadIdx.y; i < 32; i += 8)
        t[i][threadIdx.x] = s[(size_t)(k0 + i) * N + n0 + threadIdx.x];
    __syncthreads();
    #pragma unroll
    for (int i = threadIdx.y; i < 32; i += 8)
        d[(size_t)(n0 + i) * K + k0 + threadIdx.x] = __float2half_rn(t[threadIdx.x][i]);
}

// ---------------- fragment compute: 16 warps, warp tile 32x64 (mf=2, nf=8) ----------------
// ldmatrix-based fragment loads. A addr lane pattern: row = lane&15, kblk = lane>>4.
// B addr lane pattern: n = (lane>>4)*8 + (lane&7), kblk = (lane>>3)&1.
#define COMPUTE_FRAGS(AsOff_, BsOff_) do {                                             \
    uint32_t aA = sbase + (AsOff_) + (wm * 32 + (lane & 15)) * RSH + ((lane >> 4) * 8) * 2; \
    uint32_t aB = sbase + (BsOff_) + (wn * 64 + ((lane >> 4) * 8) + (lane & 7)) * RSH       \
                  + (((lane >> 3) & 1) * 8) * 2;                                        \
    _Pragma("unroll")                                                                   \
    for (int kk = 0; kk < BK; kk += 16) {                                               \
        uint32_t a[2][4], b[8][2];                                                      \
        LDSM4(a[0][0], a[0][1], a[0][2], a[0][3], aA + kk * 2);                         \
        LDSM4(a[1][0], a[1][1], a[1][2], a[1][3], aA + 16 * RSH + kk * 2);              \
        LDSM4(b[0][0], b[0][1], b[1][0], b[1][1], aB + kk * 2);                         \
        LDSM4(b[2][0], b[2][1], b[3][0], b[3][1], aB + 16 * RSH + kk * 2);              \
        LDSM4(b[4][0], b[4][1], b[5][0], b[5][1], aB + 32 * RSH + kk * 2);              \
        LDSM4(b[6][0], b[6][1], b[7][0], b[7][1], aB + 48 * RSH + kk * 2);              \
        _Pragma("unroll")                                                               \
        for (int mf = 0; mf < 2; mf++)                                                  \
            _Pragma("unroll")                                                           \
            for (int nf = 0; nf < 8; nf++)                                              \
                mma16(acc[mf][nf], a[mf], b[nf]);                                       \
    }                                                                                   \
} while (0)

// ============================================================================
// GEMM1: h = fp16(x[perm]) @ W1h[d]^T + b1 -> g_hh; per-row (sum,sumsq)
// 512 threads; A: fused gather+cvt (2-slot); B: 3-stage cp.async
// ============================================================================
__global__ __launch_bounds__(NTHREADS, 1)
void gemm1_h(const float* __restrict__ x,
             const float* __restrict__ b1) {
    extern __shared__ __align__(16) char smem[];
    uint32_t sbase = (uint32_t)__cvta_generic_to_shared(smem);
    int*    sPerm = (int*)(smem + G1_PERM);
    float2* sStat = (float2*)(smem + G1_STAT);

    int bt = blockIdx.x;
    if (bt >= g_ntiles) return;
    int dom  = g_tile_dom[bt];
    int row0 = g_tile_row[bt];
    int cnt  = g_tile_cnt[bt];
    int by   = blockIdx.y;
    int colBase = by * BN;

    int tid  = threadIdx.x;
    int lane = tid & 31, wid = tid >> 5;
    int wm = wid >> 2, wn = wid & 3;
    int lk = lane & 3, lm = lane >> 2;

    if (tid < BM) sPerm[tid] = (tid < cnt) ? g_perm[row0 + tid] : -1;
    __syncthreads();

    const __half* W1h = g_w1h + ((size_t)dom * D_HID + colBase) * D_IN;

    // A loader: row = tid>>2 (0..127), seg = tid&3 (8 floats -> 8 halfs)
    int arow = tid >> 2, aseg = tid & 3;
    int asrc = sPerm[arow];
    // B loader: n = tid>>1 (0..255), half of 64B row
    int bn = tid >> 1, bj = tid & 1;

    #define ISSUE1B(cidx) do {                                                         \
        int k0_ = (cidx) * BK;                                                         \
        uint32_t sb = sbase + OFF1_B + ((cidx) % 3) * SB_ST;                           \
        const __half* bsrc = W1h + (size_t)bn * D_IN + k0_ + bj * 16;                  \
        CP16(sb + bn * RSH + bj * 32,      bsrc);                                      \
        CP16(sb + bn * RSH + bj * 32 + 16, bsrc + 8);                                  \
        CP_COMMIT();                                                                   \
    } while (0)

    float4 xv0, xv1;
    #define LDG_A1(k0_) do {                                                           \
        if (asrc >= 0) {                                                               \
            const float* sp = x + (size_t)asrc * D_IN + (k0_) + aseg * 8;              \
            xv0 = *(const float4*)(sp);                                                \
            xv1 = *(const float4*)(sp + 4);                                            \
        } else {                                                                       \
            xv0 = make_float4(0.f, 0.f, 0.f, 0.f);                                     \
            xv1 = xv0;                                                                 \
        }                                                                              \
    } while (0)

    #define PREP_STS_A1(slot) do {                                                     \
        uint4 o;                                                                       \
        o.x = pack2(xv0.x, xv0.y); o.y = pack2(xv0.z, xv0.w);                          \
        o.z = pack2(xv1.x, xv1.y); o.w = pack2(xv1.z, xv1.w);                          \
        *(uint4*)(smem + OFF1_A + (slot) * SA_ST + arow * RSH + aseg * 16) = o;        \
    } while (0)

    float acc[2][8][4];
    #pragma unroll
    for (int i = 0; i < 2; i++)
        #pragma unroll
        for (int j = 0; j < 8; j++)
            #pragma unroll
            for (int q = 0; q < 4; q++) acc[i][j][q] = 0.f;

    ISSUE1B(0); ISSUE1B(1);
    LDG_A1(0);
    PREP_STS_A1(0);

    const int NC = D_IN / BK;  // 8
    for (int c = 0; c < NC; c++) {
        CP_WAIT1();
        __syncthreads();
        if (c + 2 < NC) ISSUE1B(c + 2); else CP_COMMIT();
        if (c + 1 < NC) LDG_A1((c + 1) * BK);
        COMPUTE_FRAGS(OFF1_A + (c & 1) * SA_ST, OFF1_B + (c % 3) * SB_ST);
        if (c + 1 < NC) PREP_STS_A1((c + 1) & 1);
    }
    #undef ISSUE1B
    #undef LDG_A1
    #undef PREP_STS_A1

    // ---- epilogue: bias add, store fp16 h, per-row stats ----
    __syncthreads();
    const float* b1d = b1 + (size_t)dom * D_HID + colBase + wn * 64;
    #pragma unroll
    for (int mf = 0; mf < 2; mf++) {
        #pragma unroll
        for (int rsel = 0; rsel < 2; rsel++) {
            int r = wm * 32 + mf * 16 + lm + rsel * 8;
            float s = 0.f, ss = 0.f;
            __half* hrow = g_hh + (size_t)(row0 + r) * D_HID + colBase + wn * 64;
            bool wr = (r < cnt);
            #pragma unroll
            for (int nf = 0; nf < 8; nf++) {
                int cc = nf * 8 + 2 * lk;
                float v0 = acc[mf][nf][rsel * 2 + 0] + __ldg(b1d + cc);
                float v1 = acc[mf][nf][rsel * 2 + 1] + __ldg(b1d + cc + 1);
                s += v0 + v1;
                ss += v0 * v0 + v1 * v1;
                if (wr) *(uint32_t*)(hrow + cc) = pack2(v0, v1);
            }
            s  += __shfl_xor_sync(0xffffffffu, s, 1);
            s  += __shfl_xor_sync(0xffffffffu, s, 2);
            ss += __shfl_xor_sync(0xffffffffu, ss, 1);
            ss += __shfl_xor_sync(0xffffffffu, ss, 2);
            if (lk == 0) sStat[r * 4 + wn] = make_float2(s, ss);
        }
    }
    __syncthreads();
    if (tid < BM && tid < cnt) {
        float s = 0.f, ss = 0.f;
        #pragma unroll
        for (int q = 0; q < 4; q++) {
            float2 p = sStat[tid * 4 + q];
            s += p.x; ss += p.y;
        }
        g_part[(size_t)(row0 + tid) * 4 + by] = make_float2(s, ss);
    }
}

// ============================================================================
// GEMM2: out[perm] = relu(LN(h)*gamma+beta) @ W2h[d]^T + b2
// 512 threads; A: fused LN loader (2-slot); B: 3-stage cp.async
// ============================================================================
__global__ __launch_bounds__(NTHREADS, 1)
void gemm2_h(const float* __restrict__ gamma,
             const float* __restrict__ beta,
             const float* __restrict__ b2,
             float* __restrict__ out) {
    extern __shared__ __align__(16) char smem[];
    uint32_t sbase = (uint32_t)__cvta_generic_to_shared(smem);
    float* sG  = (float*)(smem + G2_G);
    float* sBt = (float*)(smem + G2_B);
    float* sMu = (float*)(smem + G2_MU);
    float* sRs = (float*)(smem + G2_RS);
    int*   sPerm = (int*)(smem + G2_PERM);

    int bt = blockIdx.x;
    if (bt >= g_ntiles) return;
    int dom  = g_tile_dom[bt];
    int row0 = g_tile_row[bt];
    int cnt  = g_tile_cnt[bt];

    int tid  = threadIdx.x;
    int lane = tid & 31, wid = tid >> 5;
    int wm = wid >> 2, wn = wid & 3;
    int lk = lane & 3, lm = lane >> 2;

    for (int i = tid; i < D_HID; i += NTHREADS) {
        sG[i]  = gamma[(size_t)dom * D_HID + i];
        sBt[i] = beta[(size_t)dom * D_HID + i];
    }
    if (tid < BM) {
        sPerm[tid] = (tid < cnt) ? g_perm[row0 + tid] : -1;
        float mu = 0.f, rs = 0.f;
        if (tid < cnt) {
            float s = 0.f, ss = 0.f;
            #pragma unroll
            for (int q = 0; q < 4; q++) {
                float2 p = g_part[(size_t)(row0 + tid) * 4 + q];
                s += p.x; ss += p.y;
            }
            mu = s * (1.f / D_HID);
            float var = ss * (1.f / D_HID) - mu * mu;
            rs = rsqrtf(var + LN_EPS);
        }
        sMu[tid] = mu; sRs[tid] = rs;
    }
    __syncthreads();

    const __half* W2h = g_w2h + (size_t)dom * D_OUT * D_HID;

    // A loader: row = tid>>2, 8 halfs at (tid&3)*8
    int arow = tid >> 2, aseg = tid & 3;
    int icl = min(arow, cnt - 1);
    int iar = row0 + icl;
    float amu = sMu[icl], ars = sRs[icl];
    // B loader: n = tid>>1, half of 64B row
    int bn = tid >> 1, bj = tid & 1;

    #define ISSUE2B(cidx) do {                                                         \
        int k0_ = (cidx) * BK;                                                         \
        uint32_t sb = sbase + OFF2_B + ((cidx) % 3) * SB_ST;                           \
        const __half* bsrc = W2h + (size_t)bn * D_HID + k0_ + bj * 16;                 \
        CP16(sb + bn * RSH + bj * 32,      bsrc);                                      \
        CP16(sb + bn * RSH + bj * 32 + 16, bsrc + 8);                                  \
        CP_COMMIT();                                                                   \
    } while (0)

    uint4 hv;
    #define LDG_A2(k0_) do {                                                           \
        hv = *(const uint4*)(g_hh + (size_t)iar * D_HID + (k0_) + aseg * 8);           \
    } while (0)

    #define LN1(f, kb) fmaxf(fmaf(((f) - amu) * ars, sG[kb], sBt[kb]), 0.f)

    #define PREP_STS_A2(slot, k0_) do {                                                \
        int kb = (k0_) + aseg * 8;                                                     \
        uint32_t hw[4] = {hv.x, hv.y, hv.z, hv.w};                                     \
        uint32_t ow[4];                                                                \
        _Pragma("unroll")                                                              \
        for (int j_ = 0; j_ < 4; j_++) {                                               \
            float2 f = __half22float2(*(__half2*)&hw[j_]);                             \
            ow[j_] = pack2(LN1(f.x, kb + 2 * j_), LN1(f.y, kb + 2 * j_ + 1));          \
        }                                                                              \
        *(uint4*)(smem + OFF2_A + (slot) * SA_ST + arow * RSH + aseg * 16) =           \
            make_uint4(ow[0], ow[1], ow[2], ow[3]);                                    \
    } while (0)

    float acc[2][8][4];
    #pragma unroll
    for (int i = 0; i < 2; i++)
        #pragma unroll
        for (int j = 0; j < 8; j++)
            #pragma unroll
            for (int q = 0; q < 4; q++) acc[i][j][q] = 0.f;

    ISSUE2B(0); ISSUE2B(1);
    LDG_A2(0);
    PREP_STS_A2(0, 0);

    const int NC = D_HID / BK;  // 32
    for (int c = 0; c < NC; c++) {
        CP_WAIT1();
        __syncthreads();
        if (c + 2 < NC) ISSUE2B(c + 2); else CP_COMMIT();
        if (c + 1 < NC) LDG_A2((c + 1) * BK);
        COMPUTE_FRAGS(OFF2_A + (c & 1) * SA_ST, OFF2_B + (c % 3) * SB_ST);
        if (c + 1 < NC) PREP_STS_A2((c + 1) & 1, (c + 1) * BK);
    }
    #undef ISSUE2B
    #undef LDG_A2
    #undef LN1
    #undef PREP_STS_A2

    // ---- epilogue: bias add, scatter to out ----
    const float* b2d = b2 + (size_t)dom * D_OUT + wn * 64;
    #pragma unroll
    for (int mf = 0; mf < 2; mf++) {
        #pragma unroll
        for (int rsel = 0; rsel < 2; rsel++) {
            int r = wm * 32 + mf * 16 + lm + rsel * 8;
            int src = sPerm[r];
            if (src < 0) continue;
            float* orow = out + (size_t)src * D_OUT + wn * 64;
            #pragma unroll
            for (int nf = 0; nf < 8; nf++) {
                int cc = nf * 8 + 2 * lk;
                float v0 = acc[mf][nf][rsel * 2 + 0] + __ldg(b2d + cc);
                float v1 = acc[mf][nf][rsel * 2 + 1] + __ldg(b2d + cc + 1);
                *(float2*)(orow + cc) = make_float2(v0, v1);
            }
        }
    }
}

// ---------------- launch ----------------
extern "C" void kernel_launch(void* const* d_in, const int* in_sizes, int n_in,
                              void* d_out, int out_size) {
    const float* x     = (const float*)d_in[0];
    const int*   dom   = (const int*)  d_in[1];
    const float* W1    = (const float*)d_in[2];
    const float* b1    = (const float*)d_in[3];
    const float* gamma = (const float*)d_in[4];
    const float* beta  = (const float*)d_in[5];
    const float* W2    = (const float*)d_in[6];
    const float* b2    = (const float*)d_in[7];
    float* out = (float*)d_out;

    cudaFuncSetAttribute(gemm1_h, cudaFuncAttributeMaxDynamicSharedMemorySize, SMEM1_TOTAL);
    cudaFuncSetAttribute(gemm2_h, cudaFuncAttributeMaxDynamicSharedMemorySize, SMEM2_TOTAL);

    init_kernel<<<1, 32>>>();
    hist_kernel<<<N_ROWS / 256, 256>>>(dom);
    plan_kernel<<<1, 32>>>();
    scatter_kernel<<<N_ROWS / 256, 256>>>(dom);

    {   // weights: transpose + fp16
        __half* w1h; cudaGetSymbolAddress((void**)&w1h, g_w1h);
        __half* w2h; cudaGetSymbolAddress((void**)&w2h, g_w2h);
        dim3 blk(32, 8);
        dim3 t1(D_HID / 32, D_IN / 32, N_DOM);
        transp_h<<<t1, blk>>>(W1, w1h, D_IN, D_HID);
        dim3 t2(D_OUT / 32, D_HID / 32, N_DOM);
        transp_h<<<t2, blk>>>(W2, w2h, D_HID, D_OUT);
    }

    dim3 grid1(MAX_TILES, D_HID / BN);   // (384, 4)
    gemm1_h<<<grid1, NTHREADS, SMEM1_TOTAL>>>(x, b1);

    gemm2_h<<<MAX_TILES, NTHREADS, SMEM2_TOTAL>>>(gamma, beta, b2, out);
}